// round 4
// baseline (speedup 1.0000x reference)
#include <cuda_runtime.h>
#include <cstdint>

// VoxelHashTable: 2-level voxel hash trilinear interpolation.
// 8 lanes per QUERY; each group handles BOTH levels (2 independent
// h2v-load + gather streams per thread -> better latency hiding).
// lane c owns corner c (hash + h2v + feature chunk c).
//
// Inputs (metadata order):
//   d_in[0] query_pts : float32 (M*3)
//   d_in[1] feats0    : float32 (n0*32)
//   d_in[2] feats1    : float32 (n1*32)
//   d_in[3] h2v0      : int32   (2^20)
//   d_in[4] h2v1      : int32   (2^20)
// Output: float32 (M*64) = concat(level0, level1)

#define TSIZE 1048576u
#define TMASK (TSIZE - 1u)

__device__ __forceinline__ constexpr unsigned P0() { return 73856093u % TSIZE; }
__device__ __forceinline__ constexpr unsigned P1() { return 19349669u % TSIZE; }
__device__ __forceinline__ constexpr unsigned P2() { return 83492791u % TSIZE; }

__global__ void __launch_bounds__(256)
voxel_hash_kernel(const float* __restrict__ qpts,
                  const float* __restrict__ feats0,
                  const float* __restrict__ feats1,
                  const int*   __restrict__ h2v0,
                  const int*   __restrict__ h2v1,
                  float*       __restrict__ out,
                  int M)
{
    int t     = blockIdx.x * blockDim.x + threadIdx.x;
    int qi    = t >> 3;        // query id; grid sized exactly (M % 32 == 0)
    int lane8 = t & 7;         // corner id == feature-chunk id

    float qx = __ldg(&qpts[qi * 3 + 0]);
    float qy = __ldg(&qpts[qi * 3 + 1]);
    float qz = __ldg(&qpts[qi * 3 + 2]);

    // This lane's corner (OFFSETS ordering: [x,y,z] = bits 2,1,0 of lane8).
    int ox = (lane8 >> 2) & 1, oy = (lane8 >> 1) & 1, oz = lane8 & 1;
    unsigned hoff = (ox ? P0() : 0u) + (oy ? P1() : 0u) + (oz ? P2() : 0u);

    const float inv_res[2] = {1.0f / 0.12f, 1.0f / 0.24f};
    const int* __restrict__ h2vp[2] = {h2v0, h2v1};
    const float* __restrict__ featp[2] = {feats0, feats1};

    int   v[2];
    float wx[2][2], wy[2][2], wz[2][2];

#pragma unroll
    for (int l = 0; l < 2; ++l) {
        float sx = qx * inv_res[l];
        float sy = qy * inv_res[l];
        float sz = qz * inv_res[l];
        float fxf = floorf(sx), fyf = floorf(sy), fzf = floorf(sz);
        float frx = sx - fxf, fry = sy - fyf, frz = sz - fzf;
        int bx = (int)fxf, by = (int)fyf, bz = (int)fzf;

        unsigned hb = (unsigned)bx * P0() + (unsigned)by * P1() + (unsigned)bz * P2();
        unsigned h  = (hb + hoff) & TMASK;
        v[l] = __ldg(&h2vp[l][h]);          // two independent random loads in flight

        wx[l][0] = 1.0f - frx; wx[l][1] = frx;
        wy[l][0] = 1.0f - fry; wy[l][1] = fry;
        wz[l][0] = 1.0f - frz; wz[l][1] = frz;
    }

    // Broadcast all 16 voxel indices (both levels) up front.
    int vc[2][8];
#pragma unroll
    for (int c = 0; c < 8; ++c) {
#pragma unroll
        for (int l = 0; l < 2; ++l)
            vc[l][c] = __shfl_sync(0xffffffffu, v[l], c, 8);
    }

    float4 acc[2];
#pragma unroll
    for (int l = 0; l < 2; ++l) acc[l] = make_float4(0.f, 0.f, 0.f, 0.f);

    // Interleave both levels' gather+FMA streams per corner.
#pragma unroll
    for (int c = 0; c < 8; ++c) {
#pragma unroll
        for (int l = 0; l < 2; ++l) {
            int vcl = vc[l][c];
            if (vcl >= 0) {
                // 8 lanes * 16B = one full 128B row, single coalesced wavefront.
                float4 fv = __ldg(reinterpret_cast<const float4*>(
                                      featp[l] + (size_t)vcl * 32) + lane8);
                float wc = wx[l][(c >> 2) & 1] * wy[l][(c >> 1) & 1] * wz[l][c & 1];
                acc[l].x = fmaf(wc, fv.x, acc[l].x);
                acc[l].y = fmaf(wc, fv.y, acc[l].y);
                acc[l].z = fmaf(wc, fv.z, acc[l].z);
                acc[l].w = fmaf(wc, fv.w, acc[l].w);
            }
        }
    }

    // out row: 64 floats at out[qi*64]; level l chunk at +l*32, lane chunk +lane8*4.
    float4* op = reinterpret_cast<float4*>(out) + (size_t)qi * 16 + lane8;
    op[0] = acc[0];
    op[8] = acc[1];
}

extern "C" void kernel_launch(void* const* d_in, const int* in_sizes, int n_in,
                              void* d_out, int out_size)
{
    const float* qpts   = (const float*)d_in[0];
    const float* feats0 = (const float*)d_in[1];
    const float* feats1 = (const float*)d_in[2];
    const int*   h2v0   = (const int*)d_in[3];
    const int*   h2v1   = (const int*)d_in[4];
    float* out = (float*)d_out;

    int M = in_sizes[0] / 3;          // 500000
    long long total = 8LL * M;        // one 8-lane group per query
    int block = 256;
    int grid = (int)((total + block - 1) / block);
    voxel_hash_kernel<<<grid, block>>>(qpts, feats0, feats1, h2v0, h2v1, out, M);
}

// round 5
// speedup vs baseline: 1.5198x; 1.5198x over previous
#include <cuda_runtime.h>
#include <cstdint>

// VoxelHashTable: 2-level voxel hash trilinear interpolation.
// 8 lanes per QUERY, both levels per thread (2 independent load streams).
// All per-level state is explicit scalars (no indexed arrays) and no
// __launch_bounds__, so ptxas can allocate ~48 regs instead of squeezing
// to 32 and spilling (R4 failure mode).
//
// Inputs (metadata order):
//   d_in[0] query_pts : float32 (M*3)
//   d_in[1] feats0    : float32 (n0*32)
//   d_in[2] feats1    : float32 (n1*32)
//   d_in[3] h2v0      : int32   (2^20)
//   d_in[4] h2v1      : int32   (2^20)
// Output: float32 (M*64) = concat(level0, level1)

#define TSIZE 1048576u
#define TMASK (TSIZE - 1u)

__device__ __forceinline__ constexpr unsigned P0() { return 73856093u % TSIZE; }
__device__ __forceinline__ constexpr unsigned P1() { return 19349669u % TSIZE; }
__device__ __forceinline__ constexpr unsigned P2() { return 83492791u % TSIZE; }

__global__ void
voxel_hash_kernel(const float* __restrict__ qpts,
                  const float* __restrict__ feats0,
                  const float* __restrict__ feats1,
                  const int*   __restrict__ h2v0,
                  const int*   __restrict__ h2v1,
                  float*       __restrict__ out,
                  int M)
{
    int t     = blockIdx.x * blockDim.x + threadIdx.x;
    int qi    = t >> 3;        // query id; grid divides exactly (M % 32 == 0)
    int lane8 = t & 7;         // corner id == feature-chunk id

    float qx = qpts[qi * 3 + 0];
    float qy = qpts[qi * 3 + 1];
    float qz = qpts[qi * 3 + 2];

    // This lane's corner (OFFSETS ordering: [x,y,z] = bits 2,1,0 of lane8).
    const int ox = (lane8 >> 2) & 1, oy = (lane8 >> 1) & 1, oz = lane8 & 1;
    const unsigned hoff = (ox ? P0() : 0u) + (oy ? P1() : 0u) + (oz ? P2() : 0u);

    // ---- level 0 ----
    float sx0 = qx * (1.0f / 0.12f);
    float sy0 = qy * (1.0f / 0.12f);
    float sz0 = qz * (1.0f / 0.12f);
    float fx0 = floorf(sx0), fy0 = floorf(sy0), fz0 = floorf(sz0);
    float ax0 = sx0 - fx0, ay0 = sy0 - fy0, az0 = sz0 - fz0;   // fracs
    unsigned hb0 = (unsigned)(int)fx0 * P0() + (unsigned)(int)fy0 * P1()
                 + (unsigned)(int)fz0 * P2();
    int v0 = __ldg(&h2v0[(hb0 + hoff) & TMASK]);

    // ---- level 1 ---- (independent: both loads in flight together)
    float sx1 = qx * (1.0f / 0.24f);
    float sy1 = qy * (1.0f / 0.24f);
    float sz1 = qz * (1.0f / 0.24f);
    float fx1 = floorf(sx1), fy1 = floorf(sy1), fz1 = floorf(sz1);
    float ax1 = sx1 - fx1, ay1 = sy1 - fy1, az1 = sz1 - fz1;
    unsigned hb1 = (unsigned)(int)fx1 * P0() + (unsigned)(int)fy1 * P1()
                 + (unsigned)(int)fz1 * P2();
    int v1 = __ldg(&h2v1[(hb1 + hoff) & TMASK]);

    float bx0 = 1.0f - ax0, by0 = 1.0f - ay0, bz0 = 1.0f - az0;
    float bx1 = 1.0f - ax1, by1 = 1.0f - ay1, bz1 = 1.0f - az1;

    float4 acc0 = make_float4(0.f, 0.f, 0.f, 0.f);
    float4 acc1 = make_float4(0.f, 0.f, 0.f, 0.f);

    // Per corner: broadcast both levels' indices, gather both rows
    // (coalesced: 8 lanes * 16B = one 128B row), FMA immediately.
#pragma unroll
    for (int c = 0; c < 8; ++c) {
        int cx = (c >> 2) & 1, cy = (c >> 1) & 1, cz = c & 1;

        int vA = __shfl_sync(0xffffffffu, v0, c, 8);
        int vB = __shfl_sync(0xffffffffu, v1, c, 8);

        float wA = (cx ? ax0 : bx0) * (cy ? ay0 : by0) * (cz ? az0 : bz0);
        float wB = (cx ? ax1 : bx1) * (cy ? ay1 : by1) * (cz ? az1 : bz1);

        if (vA >= 0) {
            float4 f = __ldg(reinterpret_cast<const float4*>(
                                 feats0 + (size_t)vA * 32) + lane8);
            acc0.x = fmaf(wA, f.x, acc0.x);
            acc0.y = fmaf(wA, f.y, acc0.y);
            acc0.z = fmaf(wA, f.z, acc0.z);
            acc0.w = fmaf(wA, f.w, acc0.w);
        }
        if (vB >= 0) {
            float4 f = __ldg(reinterpret_cast<const float4*>(
                                 feats1 + (size_t)vB * 32) + lane8);
            acc1.x = fmaf(wB, f.x, acc1.x);
            acc1.y = fmaf(wB, f.y, acc1.y);
            acc1.z = fmaf(wB, f.z, acc1.z);
            acc1.w = fmaf(wB, f.w, acc1.w);
        }
    }

    // out row: 64 floats at out[qi*64]; level0 chunk +0, level1 chunk +32.
    float4* op = reinterpret_cast<float4*>(out) + (size_t)qi * 16 + lane8;
    op[0] = acc0;
    op[8] = acc1;
}

extern "C" void kernel_launch(void* const* d_in, const int* in_sizes, int n_in,
                              void* d_out, int out_size)
{
    const float* qpts   = (const float*)d_in[0];
    const float* feats0 = (const float*)d_in[1];
    const float* feats1 = (const float*)d_in[2];
    const int*   h2v0   = (const int*)d_in[3];
    const int*   h2v1   = (const int*)d_in[4];
    float* out = (float*)d_out;

    int M = in_sizes[0] / 3;          // 500000
    long long total = 8LL * M;        // one 8-lane group per query
    int block = 256;
    int grid = (int)((total + block - 1) / block);
    voxel_hash_kernel<<<grid, block>>>(qpts, feats0, feats1, h2v0, h2v1, out, M);
}